// round 2
// baseline (speedup 1.0000x reference)
#include <cuda_runtime.h>

typedef unsigned long long u64;

#define DK      128      // feature dim / GEMM K
#define NOUT    256      // A-half (128) + B-half (128)
#define TILE_M  64
#define XSTRIDE 132      // padded floats per smem X row (multiple of 4)

// Scratch: AB[n][0:128] = nodes @ W1[0:128]  (src half)
//          AB[n][128:256] = nodes @ W1[128:256] (dst half)
__device__ float4 g_AB[100000 * 64];   // 100000 rows x 256 floats = 102.4 MB

__device__ __forceinline__ u64 pk2(float x, float y) {
    u64 r; asm("mov.b64 %0, {%1, %2};" : "=l"(r) : "f"(x), "f"(y)); return r;
}
__device__ __forceinline__ u64 fma2(u64 a, u64 b, u64 c) {
    u64 d; asm("fma.rn.f32x2 %0, %1, %2, %3;" : "=l"(d) : "l"(a), "l"(b), "l"(c)); return d;
}

// ---------------------------------------------------------------------------
// Phase 1: AB = X(100K x 128) @ W1cat(128 x 256)
// Block: 256 threads, TILE_M=64 rows. Warp w handles rows w*8..w*8+7.
// Lane l handles cols {l*4..l*4+3} and {128+l*4..128+l*4+3} -> W smem reads are
// fully-coalesced LDS.128 across the warp (conflict-free).
// ---------------------------------------------------------------------------
__global__ __launch_bounds__(256, 1)
void gemm_kernel(const float* __restrict__ X, const float* __restrict__ W1, int n_nodes)
{
    extern __shared__ float smem[];
    float* sW = smem;              // [128][256]
    float* sX = smem + 128 * NOUT; // [64][XSTRIDE]

    const int tid = threadIdx.x;
    const int m0  = blockIdx.x * TILE_M;

    // Load W1cat: W1 is (256,128) row-major. cols j<128 come from W1 rows 0..127,
    // cols j>=128 come from W1 rows 128..255.
    #pragma unroll
    for (int t = 0; t < 32; ++t) {               // 8192 float4 slots / 256 threads
        int idx = tid + t * 256;
        int k   = idx >> 6;
        int j4  = (idx & 63) << 2;
        float4 v;
        if (j4 < 128) v = *(const float4*)(W1 + (size_t)k * 128 + j4);
        else          v = *(const float4*)(W1 + (size_t)(k + 128) * 128 + (j4 - 128));
        *(float4*)(sW + k * NOUT + j4) = v;
    }
    // Load X tile (zero-fill OOB rows)
    #pragma unroll
    for (int t = 0; t < 8; ++t) {                // 2048 float4 slots / 256 threads
        int idx = tid + t * 256;
        int m   = idx >> 5;
        int k4  = (idx & 31) << 2;
        float4 v = make_float4(0.f, 0.f, 0.f, 0.f);
        if (m0 + m < n_nodes) v = *(const float4*)(X + (size_t)(m0 + m) * DK + k4);
        *(float4*)(sX + m * XSTRIDE + k4) = v;
    }
    __syncthreads();

    const int lane = tid & 31;
    const int wid  = tid >> 5;

    u64 acc[8][4];
    #pragma unroll
    for (int r = 0; r < 8; ++r)
        #pragma unroll
        for (int p = 0; p < 4; ++p) acc[r][p] = 0ull;

    #pragma unroll 1
    for (int k = 0; k < DK; k += 4) {
        float4 xv[8];
        #pragma unroll
        for (int r = 0; r < 8; ++r)
            xv[r] = *(const float4*)(sX + (wid * 8 + r) * XSTRIDE + k);

        #pragma unroll
        for (int kk = 0; kk < 4; ++kk) {
            ulonglong2 wa = *(const ulonglong2*)(sW + (k + kk) * NOUT + lane * 4);
            ulonglong2 wb = *(const ulonglong2*)(sW + (k + kk) * NOUT + 128 + lane * 4);
            #pragma unroll
            for (int r = 0; r < 8; ++r) {
                float xs = (kk == 0) ? xv[r].x : (kk == 1) ? xv[r].y
                         : (kk == 2) ? xv[r].z : xv[r].w;
                u64 xx = pk2(xs, xs);
                acc[r][0] = fma2(xx, wa.x, acc[r][0]);
                acc[r][1] = fma2(xx, wa.y, acc[r][1]);
                acc[r][2] = fma2(xx, wb.x, acc[r][2]);
                acc[r][3] = fma2(xx, wb.y, acc[r][3]);
            }
        }
    }

    float* AB = (float*)g_AB;
    #pragma unroll
    for (int r = 0; r < 8; ++r) {
        int row = m0 + wid * 8 + r;
        if (row < n_nodes) {
            float* dst = AB + (size_t)row * NOUT;
            ulonglong2 v0; v0.x = acc[r][0]; v0.y = acc[r][1];
            ulonglong2 v1; v1.x = acc[r][2]; v1.y = acc[r][3];
            *(ulonglong2*)(dst + lane * 4)       = v0;  // cols lane*4..+3
            *(ulonglong2*)(dst + 128 + lane * 4) = v1;  // cols 128+lane*4..+3
        }
    }
}

// ---------------------------------------------------------------------------
// Phase 2: per edge e with (s,d): h = relu(A[s] + B[d] + b1);
// scores = h @ W2 + b2; softmax over 2 -> out[e], out[n_edges+e].
// One warp per edge; coalesced float4 gathers; butterfly shfl reduction.
// NOTE: edge_index is int32 on device (JAX downcasts int64 without x64 mode).
// ---------------------------------------------------------------------------
__global__ __launch_bounds__(256)
void edge_kernel(const int* __restrict__ eidx,
                 const float* __restrict__ b1,
                 const float* __restrict__ W2,
                 const float* __restrict__ b2,
                 float* __restrict__ out, int n_edges, int n_nodes)
{
    int e = (blockIdx.x << 3) + (threadIdx.x >> 5);
    if (e >= n_edges) return;
    const int lane = threadIdx.x & 31;

    int s = __ldg(eidx + e);
    int d = __ldg(eidx + n_edges + e);
    // defensive clamp: a bad index becomes a wrong answer, not a crash
    s = min(max(s, 0), n_nodes - 1);
    d = min(max(d, 0), n_nodes - 1);

    const float4* A4 = g_AB + (size_t)s * 64;        // row s, cols 0..127
    const float4* B4 = g_AB + (size_t)d * 64 + 32;   // row d, cols 128..255

    float4 a = __ldg(A4 + lane);
    float4 b = __ldg(B4 + lane);
    float4 c = __ldg(((const float4*)b1) + lane);

    float hx = fmaxf(a.x + b.x + c.x, 0.f);
    float hy = fmaxf(a.y + b.y + c.y, 0.f);
    float hz = fmaxf(a.z + b.z + c.z, 0.f);
    float hw = fmaxf(a.w + b.w + c.w, 0.f);

    // W2 is (128,2) row-major: float4 pairs {W2[j][0],W2[j][1],W2[j+1][0],W2[j+1][1]}
    float4 wA = __ldg(((const float4*)W2) + lane * 2);
    float4 wB = __ldg(((const float4*)W2) + lane * 2 + 1);

    float s0 = hx * wA.x + hy * wA.z + hz * wB.x + hw * wB.z;
    float s1 = hx * wA.y + hy * wA.w + hz * wB.y + hw * wB.w;

    #pragma unroll
    for (int o = 16; o; o >>= 1) {
        s0 += __shfl_xor_sync(0xffffffffu, s0, o);
        s1 += __shfl_xor_sync(0xffffffffu, s1, o);
    }

    if (lane == 0) {
        s0 += __ldg(b2 + 0);
        s1 += __ldg(b2 + 1);
        // softmax over {s0,s1}: exact identity, no max-subtraction needed
        out[e]           = 1.f / (1.f + expf(s1 - s0));
        out[n_edges + e] = 1.f / (1.f + expf(s0 - s1));
    }
}

extern "C" void kernel_launch(void* const* d_in, const int* in_sizes, int n_in,
                              void* d_out, int out_size)
{
    const float* X    = (const float*)d_in[0];
    const int*   eidx = (const int*)d_in[1];     // int32 (JAX x64 disabled)
    const float* W1   = (const float*)d_in[2];
    const float* b1   = (const float*)d_in[3];
    const float* W2   = (const float*)d_in[4];
    const float* b2   = (const float*)d_in[5];
    float* out = (float*)d_out;

    const int n_nodes = in_sizes[0] / DK;   // 100000
    const int n_edges = in_sizes[1] / 2;    // 640000

    const int smem_bytes = (128 * NOUT + TILE_M * XSTRIDE) * (int)sizeof(float); // 164864
    cudaFuncSetAttribute(gemm_kernel, cudaFuncAttributeMaxDynamicSharedMemorySize, smem_bytes);

    int gemm_blocks = (n_nodes + TILE_M - 1) / TILE_M;
    gemm_kernel<<<gemm_blocks, 256, smem_bytes>>>(X, W1, n_nodes);

    int edge_blocks = (n_edges + 7) / 8;   // 8 warps (edges) per 256-thread block
    edge_kernel<<<edge_blocks, 256>>>(eidx, b1, W2, b2, out, n_edges, n_nodes);
}

// round 3
// speedup vs baseline: 1.5594x; 1.5594x over previous
#include <cuda_runtime.h>
#include <cuda_fp16.h>

typedef unsigned long long u64;

#define DK       128
#define TILE_M   64
#define XSTRIDE  132

// AB in fp16: row n = [ A(n)+b1 | B(n) ],  256 halves = 512B per row, 51.2 MB total.
__device__ __half g_ABh[100000 * 256];

__device__ __forceinline__ u64 pk2(float x, float y) {
    u64 r; asm("mov.b64 %0, {%1, %2};" : "=l"(r) : "f"(x), "f"(y)); return r;
}
__device__ __forceinline__ u64 fma2(u64 a, u64 b, u64 c) {
    u64 d; asm("fma.rn.f32x2 %0, %1, %2, %3;" : "=l"(d) : "l"(a), "l"(b), "l"(c)); return d;
}
__device__ __forceinline__ void upk2(u64 v, float& x, float& y) {
    asm("mov.b64 {%0, %1}, %2;" : "=f"(x), "=f"(y) : "l"(v));
}

// ---------------------------------------------------------------------------
// Phase 1: one kernel instance per output half (blockIdx.y = 0 -> A, 1 -> B).
// AB[:, h*128 + c] = X @ W1[h*128 : h*128+128, c]   (+ b1 for h==0)
// 256 threads, TILE_M=64 rows, 97KB smem -> 2 blocks/SM (4 warps/SMSP).
// ---------------------------------------------------------------------------
__global__ __launch_bounds__(256, 2)
void gemm_half_kernel(const float* __restrict__ X, const float* __restrict__ W1,
                      const float* __restrict__ b1, int n_nodes)
{
    extern __shared__ float smem[];
    float* sW = smem;               // [128][128]
    float* sX = smem + 128 * 128;   // [64][XSTRIDE]

    const int tid  = threadIdx.x;
    const int m0   = blockIdx.x * TILE_M;
    const int half = blockIdx.y;

    // Load W half: sW[k][c] = W1[(half*128 + k)*128 + c]
    const float* Wsrc = W1 + (size_t)half * 128 * 128;
    #pragma unroll
    for (int t = 0; t < 16; ++t) {              // 4096 float4 / 256 threads
        int idx = tid + t * 256;
        *(float4*)(sW + idx * 4) = *(const float4*)(Wsrc + idx * 4);
    }
    // Load X tile (zero-fill OOB rows)
    #pragma unroll
    for (int t = 0; t < 8; ++t) {               // 2048 float4 / 256 threads
        int idx = tid + t * 256;
        int m   = idx >> 5;
        int k4  = (idx & 31) << 2;
        float4 v = make_float4(0.f, 0.f, 0.f, 0.f);
        if (m0 + m < n_nodes) v = *(const float4*)(X + (size_t)(m0 + m) * DK + k4);
        *(float4*)(sX + m * XSTRIDE + k4) = v;
    }
    __syncthreads();

    const int lane = tid & 31;
    const int wid  = tid >> 5;

    u64 acc[8][2];
    #pragma unroll
    for (int r = 0; r < 8; ++r) { acc[r][0] = 0ull; acc[r][1] = 0ull; }

    #pragma unroll 1
    for (int k = 0; k < DK; k += 4) {
        float4 xv[8];
        #pragma unroll
        for (int r = 0; r < 8; ++r)
            xv[r] = *(const float4*)(sX + (wid * 8 + r) * XSTRIDE + k);

        #pragma unroll
        for (int kk = 0; kk < 4; ++kk) {
            ulonglong2 w = *(const ulonglong2*)(sW + (k + kk) * 128 + lane * 4);
            #pragma unroll
            for (int r = 0; r < 8; ++r) {
                float xs = (kk == 0) ? xv[r].x : (kk == 1) ? xv[r].y
                         : (kk == 2) ? xv[r].z : xv[r].w;
                u64 xx = pk2(xs, xs);
                acc[r][0] = fma2(xx, w.x, acc[r][0]);
                acc[r][1] = fma2(xx, w.y, acc[r][1]);
            }
        }
    }

    // Fold b1 into the A half so the edge kernel never touches b1.
    float4 bv = make_float4(0.f, 0.f, 0.f, 0.f);
    if (half == 0) bv = *(const float4*)(b1 + lane * 4);

    #pragma unroll
    for (int r = 0; r < 8; ++r) {
        int row = m0 + wid * 8 + r;
        if (row < n_nodes) {
            float f0, f1, f2, f3;
            upk2(acc[r][0], f0, f1);
            upk2(acc[r][1], f2, f3);
            f0 += bv.x; f1 += bv.y; f2 += bv.z; f3 += bv.w;
            __half2 h01 = __floats2half2_rn(f0, f1);
            __half2 h23 = __floats2half2_rn(f2, f3);
            uint2 pack;
            pack.x = *(unsigned*)&h01;
            pack.y = *(unsigned*)&h23;
            *(uint2*)(g_ABh + (size_t)row * 256 + half * 128 + lane * 4) = pack;
        }
    }
}

// ---------------------------------------------------------------------------
// Phase 2: warp processes 32 consecutive edges.
// delta = relu(A'[s] + B[d]) . (W2[:,0]-W2[:,1]) + (b2[0]-b2[1])
// out[e] = sigmoid(delta), out[n+e] = sigmoid(-delta).
// Index loads + output stores coalesced; W2-diff hoisted per lane.
// ---------------------------------------------------------------------------
__global__ __launch_bounds__(256)
void edge_kernel(const int* __restrict__ eidx,
                 const float* __restrict__ W2,
                 const float* __restrict__ b2,
                 float* __restrict__ out, int n_edges, int n_nodes)
{
    const int lane = threadIdx.x & 31;
    const int wid  = threadIdx.x >> 5;
    const int base = (blockIdx.x * 8 + wid) * 32;
    if (base >= n_edges) return;

    // Hoisted per-lane constants: lane covers h components j = lane*4 .. lane*4+3.
    // W2 row-major (128,2): W2[j][0]=W2[2j], W2[j][1]=W2[2j+1].
    float4 wA = __ldg(((const float4*)W2) + lane * 2);       // W2[4l..4l+1][0..1]
    float4 wB = __ldg(((const float4*)W2) + lane * 2 + 1);   // W2[4l+2..4l+3][0..1]
    float4 wd = make_float4(wA.x - wA.y, wA.z - wA.w, wB.x - wB.y, wB.z - wB.w);
    float  b2d = __ldg(b2 + 0) - __ldg(b2 + 1);

    // Coalesced index loads for the whole 32-edge chunk.
    int el = base + lane;
    bool valid = el < n_edges;
    int si = valid ? __ldg(eidx + el) : 0;
    int di = valid ? __ldg(eidx + n_edges + el) : 0;
    si = min(max(si, 0), n_nodes - 1);
    di = min(max(di, 0), n_nodes - 1);

    float keep = 0.f;

    #pragma unroll 4
    for (int i = 0; i < 32; ++i) {
        int s = __shfl_sync(0xffffffffu, si, i);
        int d = __shfl_sync(0xffffffffu, di, i);

        uint2 av = __ldg(((const uint2*)(g_ABh + (size_t)s * 256)) + lane);
        uint2 bv = __ldg(((const uint2*)(g_ABh + (size_t)d * 256 + 128)) + lane);

        float2 a01 = __half22float2(*(__half2*)&av.x);
        float2 a23 = __half22float2(*(__half2*)&av.y);
        float2 b01 = __half22float2(*(__half2*)&bv.x);
        float2 b23 = __half22float2(*(__half2*)&bv.y);

        float h0 = fmaxf(a01.x + b01.x, 0.f);
        float h1 = fmaxf(a01.y + b01.y, 0.f);
        float h2 = fmaxf(a23.x + b23.x, 0.f);
        float h3 = fmaxf(a23.y + b23.y, 0.f);

        float dlt = h0 * wd.x + h1 * wd.y + h2 * wd.z + h3 * wd.w;

        #pragma unroll
        for (int o = 16; o; o >>= 1)
            dlt += __shfl_xor_sync(0xffffffffu, dlt, o);

        if (lane == i) keep = dlt;
    }

    if (valid) {
        float d0 = keep + b2d;                 // = s0 - s1
        float e  = expf(-d0);
        float c  = 1.f / (1.f + e);
        out[el]            = c;                // softmax[:,0]
        out[n_edges + el]  = e * c;            // softmax[:,1]
    }
}

extern "C" void kernel_launch(void* const* d_in, const int* in_sizes, int n_in,
                              void* d_out, int out_size)
{
    const float* X    = (const float*)d_in[0];
    const int*   eidx = (const int*)d_in[1];     // int32 on device
    const float* W1   = (const float*)d_in[2];
    const float* b1   = (const float*)d_in[3];
    const float* W2   = (const float*)d_in[4];
    const float* b2   = (const float*)d_in[5];
    float* out = (float*)d_out;

    const int n_nodes = in_sizes[0] / DK;   // 100000
    const int n_edges = in_sizes[1] / 2;    // 640000

    const int smem_bytes = (128 * 128 + TILE_M * XSTRIDE) * (int)sizeof(float); // 99328
    cudaFuncSetAttribute(gemm_half_kernel, cudaFuncAttributeMaxDynamicSharedMemorySize, smem_bytes);

    dim3 gemm_grid((n_nodes + TILE_M - 1) / TILE_M, 2);
    gemm_half_kernel<<<gemm_grid, 256, smem_bytes>>>(X, W1, b1, n_nodes);

    int edge_blocks = (n_edges + 255) / 256;   // 8 warps x 32 edges per block
    edge_kernel<<<edge_blocks, 256>>>(eidx, W2, b2, out, n_edges, n_nodes);
}

// round 5
// speedup vs baseline: 3.7586x; 2.4103x over previous
#include <cuda_runtime.h>
#include <cuda_fp16.h>
#include <cuda_bf16.h>
#include <cstdint>

#define DK 128

// -------- device-global scratch --------
__device__ __half g_ABh[100000 * 256];                 // fp16 [node][ A'(=A+b1) | B ]
__device__ __align__(16) unsigned char g_Wsw[65536];   // swizzled bf16 B image [N=256][K=128]

__device__ __forceinline__ uint32_t smem_u32(const void* p) {
    uint32_t a; asm("{ .reg .u64 t; cvta.to.shared.u64 t, %1; cvt.u32.u64 %0, t; }" : "=r"(a) : "l"(p));
    return a;
}
__device__ __forceinline__ uint32_t bf16x2(float lo, float hi) {
    uint32_t r; asm("cvt.rn.bf16x2.f32 %0, %1, %2;" : "=r"(r) : "f"(hi), "f"(lo)); return r;
}
__device__ __forceinline__ uint32_t f16x2(float lo, float hi) {
    __half2 h = __floats2half2_rn(lo, hi); return *(uint32_t*)&h;
}

// Row layout: 256B per row (128 bf16), 16 chunks of 16B, XOR-swizzled by row%8.
__device__ __forceinline__ uint32_t swz(int row, int kchunk) {
    return (uint32_t)(row * 256 + (((kchunk ^ row) & 7) | (kchunk & 8)) * 16);
}

// smem layout (bytes)
#define SM_B1    0                    // 512B: b1 floats
#define SM_A     1024                 // 16 KB: 64 x 128 bf16 (swizzled rows)
#define SM_B     (1024 + 16384)       // 64 KB: 256 x 128 bf16 (swizzled rows)
#define SM_STAGE 1024                 // reuse A+B after mainloop: 64 x 528B
#define SMEM_BYTES (1024 + 16384 + 65536)   // 82944

// ---------------------------------------------------------------------------
// Prep: B[n][k] = W1cat[k][n] as bf16, stored with the ldmatrix swizzle.
// ---------------------------------------------------------------------------
__global__ __launch_bounds__(256)
void w_prep_kernel(const float* __restrict__ W1)
{
    int idx = blockIdx.x * 256 + threadIdx.x;   // 8192 total, 4 k each
    if (idx >= 8192) return;
    int n  = idx >> 5;
    int k4 = (idx & 31) << 2;
    float w[4];
    #pragma unroll
    for (int j = 0; j < 4; ++j) {
        int k = k4 + j;
        w[j] = (n < 128) ? __ldg(W1 + (size_t)k * 128 + n)
                         : __ldg(W1 + (size_t)(128 + k) * 128 + (n - 128));
    }
    uint32_t off = swz(n, k4 >> 3) + (k4 & 7) * 2;
    *(uint2*)(g_Wsw + off) = make_uint2(bf16x2(w[0], w[1]), bf16x2(w[2], w[3]));
}

// ---------------------------------------------------------------------------
// Phase 1: HMMA GEMM. 256 threads, M-tile 64, N=256.
// Warp w: rows (w&3)*16 .. +15, N-half (w>>2). 128 mma.m16n8k16 per warp.
// ---------------------------------------------------------------------------
__global__ __launch_bounds__(256, 2)
void gemm_mma_kernel(const float* __restrict__ X, const float* __restrict__ b1, int n_nodes)
{
    extern __shared__ unsigned char smem[];
    const uint32_t sb = smem_u32(smem);
    const int tid  = threadIdx.x;
    const int lane = tid & 31;
    const int wid  = tid >> 5;
    const int m0   = blockIdx.x * 64;

    // b1 -> smem
    if (tid < 128) *(float*)(smem + SM_B1 + tid * 4) = __ldg(b1 + tid);

    // copy swizzled W image -> B smem (linear, coalesced)
    #pragma unroll
    for (int t = 0; t < 16; ++t) {
        int i = tid + t * 256;
        *((uint4*)(smem + SM_B) + i) = *((const uint4*)g_Wsw + i);
    }
    // X tile -> bf16, swizzled A smem (zero-fill OOB rows)
    #pragma unroll
    for (int t = 0; t < 8; ++t) {
        int i  = tid + t * 256;          // 2048 float4
        int m  = i >> 5;
        int k4 = (i & 31) << 2;
        float4 v = make_float4(0.f, 0.f, 0.f, 0.f);
        if (m0 + m < n_nodes) v = *(const float4*)(X + (size_t)(m0 + m) * DK + k4);
        uint32_t off = swz(m, k4 >> 3) + (k4 & 7) * 2;
        *(uint2*)(smem + SM_A + off) = make_uint2(bf16x2(v.x, v.y), bf16x2(v.z, v.w));
    }
    __syncthreads();

    const int half = wid >> 2;
    const int m0w  = (wid & 3) * 16;

    // ldmatrix source rows for this lane
    const int a_row = m0w + ((lane >> 3) & 1) * 8 + (lane & 7);   // x4: j=lane>>3
    const int a_koff = lane >> 4;                                  // j>>1
    const int b_rowbase = half * 128 + (lane & 7);                 // x2: lanes 0..15
    const int b_koff = (lane >> 3) & 1;

    float acc[16][4];
    #pragma unroll
    for (int nb = 0; nb < 16; ++nb)
        #pragma unroll
        for (int j = 0; j < 4; ++j) acc[nb][j] = 0.f;

    #pragma unroll 1
    for (int ks = 0; ks < 8; ++ks) {
        uint32_t a0, a1, a2, a3;
        uint32_t aaddr = sb + SM_A + swz(a_row, ks * 2 + a_koff);
        asm volatile("ldmatrix.sync.aligned.m8n8.x4.shared.b16 {%0,%1,%2,%3}, [%4];"
                     : "=r"(a0), "=r"(a1), "=r"(a2), "=r"(a3) : "r"(aaddr));

        #pragma unroll
        for (int nb = 0; nb < 16; ++nb) {
            uint32_t b0, b1r;
            uint32_t baddr = sb + SM_B + swz(b_rowbase + nb * 8, ks * 2 + b_koff);
            asm volatile("ldmatrix.sync.aligned.m8n8.x2.shared.b16 {%0,%1}, [%2];"
                         : "=r"(b0), "=r"(b1r) : "r"(baddr));
            asm volatile(
                "mma.sync.aligned.m16n8k16.row.col.f32.bf16.bf16.f32 "
                "{%0,%1,%2,%3}, {%4,%5,%6,%7}, {%8,%9}, {%0,%1,%2,%3};"
                : "+f"(acc[nb][0]), "+f"(acc[nb][1]), "+f"(acc[nb][2]), "+f"(acc[nb][3])
                : "r"(a0), "r"(a1), "r"(a2), "r"(a3), "r"(b0), "r"(b1r));
        }
    }
    __syncthreads();   // A/B smem dead; reuse as staging

    // Epilogue: +b1 on half 0, fp16 pack, staged conflict-free in smem.
    {
        const int mA = m0w + (lane >> 2);
        const int cq = (lane & 3) * 2;
        #pragma unroll
        for (int nb = 0; nb < 16; ++nb) {
            int n = nb * 8 + cq;                // col within the 128-half
            float add0 = 0.f, add1 = 0.f;
            if (half == 0) {
                float2 bb = *(const float2*)(smem + SM_B1 + n * 4);
                add0 = bb.x; add1 = bb.y;
            }
            uint32_t lo = f16x2(acc[nb][0] + add0, acc[nb][1] + add1);
            uint32_t hi = f16x2(acc[nb][2] + add0, acc[nb][3] + add1);
            uint32_t col = (half * 128 + n) * 2;
            *(uint32_t*)(smem + SM_STAGE + mA * 528 + col)       = lo;
            *(uint32_t*)(smem + SM_STAGE + (mA + 8) * 528 + col) = hi;
        }
    }
    __syncthreads();

    // Coalesced STG: 64 rows x 512B contiguous in g_ABh.
    uint4* out4 = (uint4*)(g_ABh) + (size_t)m0 * 32;
    #pragma unroll
    for (int t = 0; t < 8; ++t) {
        int i   = tid + t * 256;          // 2048 uint4
        int row = i >> 5;
        int c4  = i & 31;
        if (m0 + row < n_nodes)
            out4[(size_t)row * 32 + c4] = *(const uint4*)(smem + SM_STAGE + row * 528 + c4 * 16);
    }
}

// ---------------------------------------------------------------------------
// Phase 2: unchanged (38 us, L2-gather bound).
// ---------------------------------------------------------------------------
__global__ __launch_bounds__(256)
void edge_kernel(const int* __restrict__ eidx,
                 const float* __restrict__ W2,
                 const float* __restrict__ b2,
                 float* __restrict__ out, int n_edges, int n_nodes)
{
    const int lane = threadIdx.x & 31;
    const int wid  = threadIdx.x >> 5;
    const int base = (blockIdx.x * 8 + wid) * 32;
    if (base >= n_edges) return;

    float4 wA = __ldg(((const float4*)W2) + lane * 2);
    float4 wB = __ldg(((const float4*)W2) + lane * 2 + 1);
    float4 wd = make_float4(wA.x - wA.y, wA.z - wA.w, wB.x - wB.y, wB.z - wB.w);
    float  b2d = __ldg(b2 + 0) - __ldg(b2 + 1);

    int el = base + lane;
    bool valid = el < n_edges;
    int si = valid ? __ldg(eidx + el) : 0;
    int di = valid ? __ldg(eidx + n_edges + el) : 0;
    si = min(max(si, 0), n_nodes - 1);
    di = min(max(di, 0), n_nodes - 1);

    float keep = 0.f;
    #pragma unroll 4
    for (int i = 0; i < 32; ++i) {
        int s = __shfl_sync(0xffffffffu, si, i);
        int d = __shfl_sync(0xffffffffu, di, i);

        uint2 av = __ldg(((const uint2*)(g_ABh + (size_t)s * 256)) + lane);
        uint2 bv = __ldg(((const uint2*)(g_ABh + (size_t)d * 256 + 128)) + lane);

        float2 a01 = __half22float2(*(__half2*)&av.x);
        float2 a23 = __half22float2(*(__half2*)&av.y);
        float2 b01 = __half22float2(*(__half2*)&bv.x);
        float2 b23 = __half22float2(*(__half2*)&bv.y);

        float h0 = fmaxf(a01.x + b01.x, 0.f);
        float h1 = fmaxf(a01.y + b01.y, 0.f);
        float h2 = fmaxf(a23.x + b23.x, 0.f);
        float h3 = fmaxf(a23.y + b23.y, 0.f);

        float dlt = h0 * wd.x + h1 * wd.y + h2 * wd.z + h3 * wd.w;
        #pragma unroll
        for (int o = 16; o; o >>= 1)
            dlt += __shfl_xor_sync(0xffffffffu, dlt, o);
        if (lane == i) keep = dlt;
    }

    if (valid) {
        float d0 = keep + b2d;
        float e  = expf(-d0);
        float c  = 1.f / (1.f + e);
        out[el]           = c;
        out[n_edges + el] = e * c;
    }
}

extern "C" void kernel_launch(void* const* d_in, const int* in_sizes, int n_in,
                              void* d_out, int out_size)
{
    const float* X    = (const float*)d_in[0];
    const int*   eidx = (const int*)d_in[1];     // int32 on device
    const float* W1   = (const float*)d_in[2];
    const float* b1   = (const float*)d_in[3];
    const float* W2   = (const float*)d_in[4];
    const float* b2   = (const float*)d_in[5];
    float* out = (float*)d_out;

    const int n_nodes = in_sizes[0] / DK;   // 100000
    const int n_edges = in_sizes[1] / 2;    // 640000

    w_prep_kernel<<<32, 256>>>(W1);

    cudaFuncSetAttribute(gemm_mma_kernel, cudaFuncAttributeMaxDynamicSharedMemorySize, SMEM_BYTES);
    int gemm_blocks = (n_nodes + 63) / 64;   // 1563
    gemm_mma_kernel<<<gemm_blocks, 256, SMEM_BYTES>>>(X, b1, n_nodes);

    int edge_blocks = (n_edges + 255) / 256;
    edge_kernel<<<edge_blocks, 256>>>(eidx, W2, b2, out, n_edges, n_nodes);
}

// round 6
// speedup vs baseline: 3.8652x; 1.0284x over previous
#include <cuda_runtime.h>
#include <cuda_fp16.h>
#include <cuda_bf16.h>
#include <cstdint>

#define DK 128

// -------- device-global scratch --------
__device__ __half g_ABh[100000 * 256];                 // fp16 [node][ A'(=A+b1) | B ]
__device__ __align__(16) unsigned char g_Wsw[65536];   // swizzled bf16 B image [N=256][K=128]

__device__ __forceinline__ uint32_t smem_u32(const void* p) {
    uint32_t a; asm("{ .reg .u64 t; cvta.to.shared.u64 t, %1; cvt.u32.u64 %0, t; }" : "=r"(a) : "l"(p));
    return a;
}
__device__ __forceinline__ uint32_t bf16x2(float lo, float hi) {
    uint32_t r; asm("cvt.rn.bf16x2.f32 %0, %1, %2;" : "=r"(r) : "f"(hi), "f"(lo)); return r;
}
__device__ __forceinline__ uint32_t f16x2(float lo, float hi) {
    __half2 h = __floats2half2_rn(lo, hi); return *(uint32_t*)&h;
}

// Row layout: 256B per row (128 bf16), 16 chunks of 16B, XOR-swizzled by row%8.
__device__ __forceinline__ uint32_t swz(int row, int kchunk) {
    return (uint32_t)(row * 256 + (((kchunk ^ row) & 7) | (kchunk & 8)) * 16);
}

// smem layout (bytes)
#define SM_B1    0                    // 512B: b1 floats
#define SM_A     1024                 // 16 KB: 64 x 128 bf16 (swizzled rows)
#define SM_B     (1024 + 16384)       // 64 KB: 256 x 128 bf16 (swizzled rows)
#define SM_STAGE 1024                 // reuse A+B after mainloop: 64 x 528B
#define SMEM_BYTES (1024 + 16384 + 65536)   // 82944

// ---------------------------------------------------------------------------
// Prep: B[n][k] = W1cat[k][n] as bf16, swizzled. One bf16x2 per thread.
// ---------------------------------------------------------------------------
__global__ __launch_bounds__(256)
void w_prep_kernel(const float* __restrict__ W1)
{
    int idx = blockIdx.x * 256 + threadIdx.x;   // 16384 threads
    if (idx >= 16384) return;
    int n  = idx >> 6;            // 0..255
    int k2 = (idx & 63) << 1;     // 0,2,..,126
    float w0, w1;
    if (n < 128) {
        w0 = __ldg(W1 + (size_t)k2 * 128 + n);
        w1 = __ldg(W1 + (size_t)(k2 + 1) * 128 + n);
    } else {
        w0 = __ldg(W1 + (size_t)(128 + k2) * 128 + (n - 128));
        w1 = __ldg(W1 + (size_t)(129 + k2) * 128 + (n - 128));
    }
    uint32_t off = swz(n, k2 >> 3) + (k2 & 7) * 2;
    *(uint32_t*)(g_Wsw + off) = bf16x2(w0, w1);
}

// ---------------------------------------------------------------------------
// Phase 1: HMMA GEMM. 256 threads, M-tile 64, N=256.
// Warp w: rows (w&3)*16, N-half (w>>2). B loaded via ldmatrix.x4 (2 nb / load).
// ---------------------------------------------------------------------------
__global__ __launch_bounds__(256, 2)
void gemm_mma_kernel(const float* __restrict__ X, const float* __restrict__ b1, int n_nodes)
{
    extern __shared__ unsigned char smem[];
    const uint32_t sb = smem_u32(smem);
    const int tid  = threadIdx.x;
    const int lane = tid & 31;
    const int wid  = tid >> 5;
    const int m0   = blockIdx.x * 64;

    if (tid < 128) *(float*)(smem + SM_B1 + tid * 4) = __ldg(b1 + tid);

    #pragma unroll
    for (int t = 0; t < 16; ++t) {
        int i = tid + t * 256;
        *((uint4*)(smem + SM_B) + i) = *((const uint4*)g_Wsw + i);
    }
    #pragma unroll
    for (int t = 0; t < 8; ++t) {
        int i  = tid + t * 256;
        int m  = i >> 5;
        int k4 = (i & 31) << 2;
        float4 v = make_float4(0.f, 0.f, 0.f, 0.f);
        if (m0 + m < n_nodes) v = *(const float4*)(X + (size_t)(m0 + m) * DK + k4);
        uint32_t off = swz(m, k4 >> 3) + (k4 & 7) * 2;
        *(uint2*)(smem + SM_A + off) = make_uint2(bf16x2(v.x, v.y), bf16x2(v.z, v.w));
    }
    __syncthreads();

    const int half = wid >> 2;
    const int m0w  = (wid & 3) * 16;

    const int a_row     = m0w + ((lane >> 3) & 1) * 8 + (lane & 7);
    const int a_koff    = lane >> 4;
    const int b_rowbase = half * 128 + ((lane >> 4) & 1) * 8 + (lane & 7); // x4: 16 n-rows
    const int b_koff    = (lane >> 3) & 1;

    float acc[16][4];
    #pragma unroll
    for (int nb = 0; nb < 16; ++nb)
        #pragma unroll
        for (int j = 0; j < 4; ++j) acc[nb][j] = 0.f;

    #pragma unroll 1
    for (int ks = 0; ks < 8; ++ks) {
        uint32_t a0, a1, a2, a3;
        uint32_t aaddr = sb + SM_A + swz(a_row, ks * 2 + a_koff);
        asm volatile("ldmatrix.sync.aligned.m8n8.x4.shared.b16 {%0,%1,%2,%3}, [%4];"
                     : "=r"(a0), "=r"(a1), "=r"(a2), "=r"(a3) : "r"(aaddr));

        #pragma unroll
        for (int nb16 = 0; nb16 < 8; ++nb16) {
            uint32_t b0, b1r, b2r, b3r;
            uint32_t baddr = sb + SM_B + swz(b_rowbase + nb16 * 16, ks * 2 + b_koff);
            asm volatile("ldmatrix.sync.aligned.m8n8.x4.shared.b16 {%0,%1,%2,%3}, [%4];"
                         : "=r"(b0), "=r"(b1r), "=r"(b2r), "=r"(b3r) : "r"(baddr));
            asm volatile(
                "mma.sync.aligned.m16n8k16.row.col.f32.bf16.bf16.f32 "
                "{%0,%1,%2,%3}, {%4,%5,%6,%7}, {%8,%9}, {%0,%1,%2,%3};"
                : "+f"(acc[2*nb16][0]), "+f"(acc[2*nb16][1]), "+f"(acc[2*nb16][2]), "+f"(acc[2*nb16][3])
                : "r"(a0), "r"(a1), "r"(a2), "r"(a3), "r"(b0), "r"(b1r));
            asm volatile(
                "mma.sync.aligned.m16n8k16.row.col.f32.bf16.bf16.f32 "
                "{%0,%1,%2,%3}, {%4,%5,%6,%7}, {%8,%9}, {%0,%1,%2,%3};"
                : "+f"(acc[2*nb16+1][0]), "+f"(acc[2*nb16+1][1]), "+f"(acc[2*nb16+1][2]), "+f"(acc[2*nb16+1][3])
                : "r"(a0), "r"(a1), "r"(a2), "r"(a3), "r"(b2r), "r"(b3r));
        }
    }
    __syncthreads();   // A/B smem dead; reuse as staging

    {   // Epilogue: +b1 on half 0, fp16 pack, conflict-free staging.
        const int mA = m0w + (lane >> 2);
        const int cq = (lane & 3) * 2;
        #pragma unroll
        for (int nb = 0; nb < 16; ++nb) {
            int n = nb * 8 + cq;
            float add0 = 0.f, add1 = 0.f;
            if (half == 0) {
                float2 bb = *(const float2*)(smem + SM_B1 + n * 4);
                add0 = bb.x; add1 = bb.y;
            }
            uint32_t lo = f16x2(acc[nb][0] + add0, acc[nb][1] + add1);
            uint32_t hi = f16x2(acc[nb][2] + add0, acc[nb][3] + add1);
            uint32_t col = (half * 128 + n) * 2;
            *(uint32_t*)(smem + SM_STAGE + mA * 528 + col)       = lo;
            *(uint32_t*)(smem + SM_STAGE + (mA + 8) * 528 + col) = hi;
        }
    }
    __syncthreads();

    uint4* out4 = (uint4*)(g_ABh) + (size_t)m0 * 32;
    #pragma unroll
    for (int t = 0; t < 8; ++t) {
        int i   = tid + t * 256;
        int row = i >> 5;
        int c4  = i & 31;
        if (m0 + row < n_nodes)
            out4[(size_t)row * 32 + c4] = *(const uint4*)(smem + SM_STAGE + row * 528 + c4 * 16);
    }
}

// ---------------------------------------------------------------------------
// Phase 2: half-warp per edge. 2 edges per warp iteration; uint4 gathers,
// half2 add+relu, fp32 dot, 4-level shfl reduction, smem result exchange.
// ---------------------------------------------------------------------------
__global__ __launch_bounds__(256)
void edge_kernel(const int* __restrict__ eidx,
                 const float* __restrict__ W2,
                 const float* __restrict__ b2,
                 float* __restrict__ out, int n_edges, int n_nodes)
{
    __shared__ float sres[8][32];

    const int lane = threadIdx.x & 31;
    const int wid  = threadIdx.x >> 5;
    const int base = (blockIdx.x * 8 + wid) * 32;
    if (base >= n_edges) return;

    const int hl = lane & 15;   // lane within half-warp: components hl*8 .. hl*8+7
    const int hw = lane >> 4;   // edge parity handled by this half-warp

    // Hoisted per-lane W2 diffs for components j = hl*8 .. hl*8+7.
    float wd[8];
    #pragma unroll
    for (int t = 0; t < 4; ++t) {
        float4 w = __ldg(((const float4*)W2) + hl * 4 + t);  // rows hl*8+2t, hl*8+2t+1
        wd[2*t]   = w.x - w.y;
        wd[2*t+1] = w.z - w.w;
    }
    const float b2d = __ldg(b2 + 0) - __ldg(b2 + 1);

    int el = base + lane;
    bool valid = el < n_edges;
    int si = valid ? __ldg(eidx + el) : 0;
    int di = valid ? __ldg(eidx + n_edges + el) : 0;
    si = min(max(si, 0), n_nodes - 1);
    di = min(max(di, 0), n_nodes - 1);

    const __half2 z2 = __float2half2_rn(0.f);

    #pragma unroll 2
    for (int i = 0; i < 16; ++i) {
        int s = __shfl_sync(0xffffffffu, si, 2 * i + hw);
        int d = __shfl_sync(0xffffffffu, di, 2 * i + hw);

        uint4 av = __ldg(((const uint4*)(g_ABh + (size_t)s * 256)) + hl);
        uint4 bv = __ldg(((const uint4*)(g_ABh + (size_t)d * 256 + 128)) + hl);

        __half2 h0 = __hmax2(__hadd2(*(__half2*)&av.x, *(__half2*)&bv.x), z2);
        __half2 h1 = __hmax2(__hadd2(*(__half2*)&av.y, *(__half2*)&bv.y), z2);
        __half2 h2 = __hmax2(__hadd2(*(__half2*)&av.z, *(__half2*)&bv.z), z2);
        __half2 h3 = __hmax2(__hadd2(*(__half2*)&av.w, *(__half2*)&bv.w), z2);

        float2 f0 = __half22float2(h0);
        float2 f1 = __half22float2(h1);
        float2 f2 = __half22float2(h2);
        float2 f3 = __half22float2(h3);

        float dlt = f0.x * wd[0];
        dlt = fmaf(f0.y, wd[1], dlt);
        dlt = fmaf(f1.x, wd[2], dlt);
        dlt = fmaf(f1.y, wd[3], dlt);
        dlt = fmaf(f2.x, wd[4], dlt);
        dlt = fmaf(f2.y, wd[5], dlt);
        dlt = fmaf(f3.x, wd[6], dlt);
        dlt = fmaf(f3.y, wd[7], dlt);

        // reduce within 16-lane group (offsets < 16 stay inside the group)
        #pragma unroll
        for (int o = 8; o; o >>= 1)
            dlt += __shfl_xor_sync(0xffffffffu, dlt, o);

        if (hl == 0) sres[wid][2 * i + hw] = dlt;
    }
    __syncwarp();

    if (valid) {
        float d0 = sres[wid][lane] + b2d;     // = s0 - s1
        float e  = expf(-d0);
        float c  = 1.f / (1.f + e);
        out[el]           = c;
        out[n_edges + el] = e * c;
    }
}

extern "C" void kernel_launch(void* const* d_in, const int* in_sizes, int n_in,
                              void* d_out, int out_size)
{
    const float* X    = (const float*)d_in[0];
    const int*   eidx = (const int*)d_in[1];     // int32 on device
    const float* W1   = (const float*)d_in[2];
    const float* b1   = (const float*)d_in[3];
    const float* W2   = (const float*)d_in[4];
    const float* b2   = (const float*)d_in[5];
    float* out = (float*)d_out;

    const int n_nodes = in_sizes[0] / DK;   // 100000
    const int n_edges = in_sizes[1] / 2;    // 640000

    w_prep_kernel<<<64, 256>>>(W1);

    cudaFuncSetAttribute(gemm_mma_kernel, cudaFuncAttributeMaxDynamicSharedMemorySize, SMEM_BYTES);
    int gemm_blocks = (n_nodes + 63) / 64;   // 1563
    gemm_mma_kernel<<<gemm_blocks, 256, SMEM_BYTES>>>(X, b1, n_nodes);

    int edge_blocks = (n_edges + 255) / 256;
    edge_kernel<<<edge_blocks, 256>>>(eidx, W2, b2, out, n_edges, n_nodes);
}